// round 14
// baseline (speedup 1.0000x reference)
#include <cuda_runtime.h>
#include <cuda_fp16.h>
#include <cstdint>

#define BDIM 16384
#define CDIM 1024
#define DDIM 128
#define NSM 148
#define LOG2E 1.4426950408889634f

// ------------------------------- scratch -------------------------------
__device__ float s_theta[BDIM * DDIM];
__device__ float s_phi[BDIM * DDIM];
__device__ float s_g[BDIM * DDIM];
__device__ float s_y[BDIM * DDIM];
__device__ int d_done[128];

__device__ __half s_gw[DDIM * CDIM];
__device__ __half s_thw[DDIM * CDIM];
__device__ __half s_phw[DDIM * CDIM];
__device__ __half s_Ww[CDIM * DDIM];

// ------------------------------- helpers -------------------------------
__device__ __forceinline__ unsigned pkh(__half a, __half b) {
    return (unsigned)__half_as_ushort(a) | ((unsigned)__half_as_ushort(b) << 16);
}
__device__ __forceinline__ void ldsm4(uint32_t* r, uint32_t addr) {
    asm volatile("ldmatrix.sync.aligned.m8n8.x4.shared.b16 {%0,%1,%2,%3}, [%4];"
                 : "=r"(r[0]), "=r"(r[1]), "=r"(r[2]), "=r"(r[3]) : "r"(addr));
}
__device__ __forceinline__ void mma16816(float* c, const uint32_t* a, uint32_t b0, uint32_t b1) {
    asm volatile(
        "mma.sync.aligned.m16n8k16.row.col.f32.f16.f16.f32 "
        "{%0,%1,%2,%3}, {%4,%5,%6,%7}, {%8,%9}, {%0,%1,%2,%3};"
        : "+f"(c[0]), "+f"(c[1]), "+f"(c[2]), "+f"(c[3])
        : "r"(a[0]), "r"(a[1]), "r"(a[2]), "r"(a[3]), "r"(b0), "r"(b1));
}
__device__ __forceinline__ void cp16(uint32_t dst, const void* src) {
    asm volatile("cp.async.cg.shared.global [%0], [%1], 16;" :: "r"(dst), "l"(src));
}
#define CP_COMMIT() asm volatile("cp.async.commit_group;")
#define CP_WAIT1()  asm volatile("cp.async.wait_group 1;")
__device__ __forceinline__ float ex2f(float x) {
    float r; asm("ex2.approx.ftz.f32 %0, %1;" : "=f"(r) : "f"(x)); return r;
}

// ---------------- fused weight fp16 convert ----------------
__global__ void split4_kernel(const float* __restrict__ w0, const float* __restrict__ w1,
                              const float* __restrict__ w2, const float* __restrict__ w3) {
    int wsel = blockIdx.y;
    const float* in = wsel == 0 ? w0 : wsel == 1 ? w1 : wsel == 2 ? w2 : w3;
    __half* hp = wsel == 0 ? s_gw : wsel == 1 ? s_thw : wsel == 2 ? s_phw : s_Ww;
    const int n4 = DDIM * CDIM / 4;
    const float4* in4 = reinterpret_cast<const float4*>(in);
    uint2* h2 = reinterpret_cast<uint2*>(hp);
    for (int i = blockIdx.x * blockDim.x + threadIdx.x; i < n4; i += gridDim.x * blockDim.x) {
        float4 v = in4[i];
        h2[i] = make_uint2(pkh(__float2half_rn(v.x), __float2half_rn(v.y)),
                           pkh(__float2half_rn(v.z), __float2half_rn(v.w)));
    }
}

// ---------------- fp16 GEMM mainloop (proven tiling) ----------------
#define SAP 40
#define oW 10240u
#define GSMEM 30720

__device__ __forceinline__ void gemm_mainloop(
    const float* __restrict__ A, int K, int NC,
    const __half* __restrict__ W, unsigned char* smem, float acc[2][8][4]) {
    const int tid = threadIdx.x, lane = tid & 31, wid = tid >> 5;
    const int wm = (wid & 3) * 32, wn = (wid >> 2) * 64;
    const uint32_t sbase = (uint32_t)__cvta_generic_to_shared(smem);

    float4 stage[4];
    {
#pragma unroll
        for (int i = 0; i < 4; i++) {
            int q = tid + 256 * i;
            stage[i] = *reinterpret_cast<const float4*>(
                &A[(size_t)(q >> 3) * K + (q & 7) * 4]);
        }
#pragma unroll
        for (int i = 0; i < 2; i++) {
            int q = tid + 256 * i;
            int r = q >> 2, cc = q & 3;
            cp16(sbase + oW + (uint32_t)(r * SAP + cc * 8) * 2,
                 W + (size_t)r * K + cc * 8);
        }
        CP_COMMIT();
    }

    for (int c = 0; c < NC; c++) {
#pragma unroll
        for (int i = 0; i < 4; i++) {
            int q = tid + 256 * i;
            int r = q >> 3, c4 = q & 7;
            float4 v = stage[i];
            *reinterpret_cast<uint2*>(smem + (size_t)(r * SAP + c4 * 4) * 2) =
                make_uint2(pkh(__float2half_rn(v.x), __float2half_rn(v.y)),
                           pkh(__float2half_rn(v.z), __float2half_rn(v.w)));
        }
        if (c + 1 < NC) {
            int kk = (c + 1) * 32, buf = (c + 1) & 1;
#pragma unroll
            for (int i = 0; i < 4; i++) {
                int q = tid + 256 * i;
                stage[i] = *reinterpret_cast<const float4*>(
                    &A[(size_t)(q >> 3) * K + kk + (q & 7) * 4]);
            }
#pragma unroll
            for (int i = 0; i < 2; i++) {
                int q = tid + 256 * i;
                int r = q >> 2, cc = q & 3;
                cp16(sbase + oW + (uint32_t)buf * 10240u + (uint32_t)(r * SAP + cc * 8) * 2,
                     W + (size_t)r * K + kk + cc * 8);
            }
        }
        CP_COMMIT();
        CP_WAIT1();
        __syncthreads();

        const uint32_t wb = sbase + oW + (uint32_t)(c & 1) * 10240u;
#pragma unroll
        for (int ks = 0; ks < 2; ks++) {
            uint32_t ah[2][4], wf[4][4];
#pragma unroll
            for (int mt = 0; mt < 2; mt++) {
                uint32_t aoff = (uint32_t)((wm + mt * 16 + (lane & 15)) * SAP +
                                           ks * 16 + (lane >> 4) * 8) * 2;
                ldsm4(ah[mt], sbase + aoff);
            }
#pragma unroll
            for (int p = 0; p < 4; p++) {
                uint32_t woff = (uint32_t)((wn + p * 16 + (lane & 7) + ((lane >> 4) & 1) * 8) * SAP +
                                           ks * 16 + ((lane >> 3) & 1) * 8) * 2;
                ldsm4(wf[p], wb + woff);
            }
#pragma unroll
            for (int mt = 0; mt < 2; mt++)
#pragma unroll
                for (int p = 0; p < 4; p++) {
                    mma16816(acc[mt][2 * p], ah[mt], wf[p][0], wf[p][1]);
                    mma16816(acc[mt][2 * p + 1], ah[mt], wf[p][2], wf[p][3]);
                }
        }
        __syncthreads();
    }
}

// ---------------- fused proj + attn: CTA-role producer/consumer overlap ----------------
// grid 296 = 2 CTAs/SM: bids 0..147 produce proj tiles (tensor pipe),
// bids 148..295 consume 8-row attention units (MUFU pipe). One of each per SM.
__global__ void __launch_bounds__(256, 2)
fused_proj_attn(const float* __restrict__ x0, const float* __restrict__ x1,
                const float* __restrict__ gb, const float* __restrict__ thb,
                const float* __restrict__ phb) {
    extern __shared__ unsigned char smem[];
    const int bid = blockIdx.x;
    const int tid = threadIdx.x, lane = tid & 31, wid = tid >> 5;

    if (bid < NSM) {
        // ---------------- producer: proj tiles t = 3*bm + proj ----------------
        for (int t = bid; t < 384; t += NSM) {
            int bm = t / 3, pz = t - 3 * bm;
            const float* A = (pz == 0 ? x0 : x1) + (size_t)bm * 128 * CDIM;
            const __half* W = pz == 0 ? s_gw : pz == 1 ? s_thw : s_phw;
            const float* bias = pz == 0 ? gb : pz == 1 ? thb : phb;
            float* outp = (pz == 0 ? s_g : pz == 1 ? s_theta : s_phi) +
                          (size_t)bm * 128 * DDIM;

            float acc[2][8][4];
#pragma unroll
            for (int a = 0; a < 2; a++)
#pragma unroll
                for (int b = 0; b < 8; b++)
#pragma unroll
                    for (int c = 0; c < 4; c++) acc[a][b][c] = 0.f;

            gemm_mainloop(A, CDIM, 32, W, smem, acc);

            const int wm = (wid & 3) * 32, wn = (wid >> 2) * 64;
#pragma unroll
            for (int mt = 0; mt < 2; mt++) {
                int r0 = wm + mt * 16 + (lane >> 2);
#pragma unroll
                for (int nt = 0; nt < 8; nt++) {
                    int ccol = wn + nt * 8 + (lane & 3) * 2;
                    float2 v0 = make_float2(acc[mt][nt][0] + bias[ccol],
                                            acc[mt][nt][1] + bias[ccol + 1]);
                    float2 v1 = make_float2(acc[mt][nt][2] + bias[ccol],
                                            acc[mt][nt][3] + bias[ccol + 1]);
                    *reinterpret_cast<float2*>(&outp[(size_t)r0 * DDIM + ccol]) = v0;
                    *reinterpret_cast<float2*>(&outp[(size_t)(r0 + 8) * DDIM + ccol]) = v1;
                }
            }
            __threadfence();
            __syncthreads();
            if (tid == 0) atomicAdd(&d_done[bm], 1);
        }
    } else {
        // ---------------- consumer: attention, 8 rows per unit ----------------
        float* sth = reinterpret_cast<float*>(smem);           // 8x128
        float* sg  = sth + 1024;
        float* sph = sg + 1024;
        for (int u = bid - NSM; u < 2048; u += NSM) {
            int bm = u >> 4;
            if (tid == 0) {
                while (atomicAdd(&d_done[bm], 0) < 3) __nanosleep(64);
            }
            __syncthreads();

            const size_t rbase = (size_t)u * 8 * 128;
            float4 thv = reinterpret_cast<const float4*>(s_theta + rbase)[tid];
            reinterpret_cast<float4*>(sth)[tid] = thv;
            reinterpret_cast<float4*>(sg)[tid]  = reinterpret_cast<const float4*>(s_g + rbase)[tid];
            reinterpret_cast<float4*>(sph)[tid] = reinterpret_cast<const float4*>(s_phi + rbase)[tid];
            __syncthreads();

            const int w = wid, l = lane;           // warp w -> row w (8 rows)
            const float* th = sth + w * 128;
            const float* gg = sg + w * 128;
            const float* ph = sph + w * 128;

            float a0 = th[l], a1 = th[l + 32], a2 = th[l + 64], a3 = th[l + 96];
            float mx = fmaxf(fmaxf(a0, a1), fmaxf(a2, a3));
            float mn = fminf(fminf(a0, a1), fminf(a2, a3));
#pragma unroll
            for (int off = 16; off >= 1; off >>= 1) {
                mx = fmaxf(mx, __shfl_xor_sync(0xffffffffu, mx, off));
                mn = fminf(mn, __shfl_xor_sync(0xffffffffu, mn, off));
            }
            float sc[4], m2n[4], num[4], den[4];
#pragma unroll
            for (int q = 0; q < 4; q++) {
                sc[q] = ph[l + 32 * q] * LOG2E;
                m2n[q] = -sc[q] * (sc[q] >= 0.f ? mx : mn);
                num[q] = 0.f; den[q] = 0.f;
            }
#pragma unroll 8
            for (int j = 0; j < 128; j += 4) {
                float4 tv = *reinterpret_cast<const float4*>(&th[j]);
                float4 gv = *reinterpret_cast<const float4*>(&gg[j]);
                float t_[4] = {tv.x, tv.y, tv.z, tv.w};
                float g_[4] = {gv.x, gv.y, gv.z, gv.w};
#pragma unroll
                for (int e = 0; e < 4; e++) {
#pragma unroll
                    for (int q = 0; q < 4; q++) {
                        float ex = ex2f(fmaf(sc[q], t_[e], m2n[q]));
                        num[q] = fmaf(ex, g_[e], num[q]);
                        den[q] += ex;
                    }
                }
            }
#pragma unroll
            for (int q = 0; q < 4; q++)
                s_y[rbase + (size_t)w * 128 + l + 32 * q] = num[q] / den[q];
            __syncthreads();   // smem reuse next unit
        }
    }
}

// ---------------- out GEMM (R10-proven: smem-staged coalesced epilogue) ----------------
#define EPS 132
#define OUT_STAGE (20480u)
#define OUT_SMEM (20480 + 128 * EPS * 4)

__global__ void __launch_bounds__(256, 2)
out_gemm(const float* __restrict__ Wb, const float* __restrict__ x0, float* __restrict__ out) {
    extern __shared__ unsigned char smem[];
    size_t n0 = (size_t)blockIdx.x * 128;
    size_t bm = (size_t)blockIdx.y * 128;
    const float* A = s_y + bm * DDIM;
    const __half* W = s_Ww + n0 * DDIM;
    const float* resid = x0 + bm * CDIM + n0;
    float* outp = out + bm * CDIM + n0;
    const float* bias = Wb + n0;

    float acc[2][8][4];
#pragma unroll
    for (int a = 0; a < 2; a++)
#pragma unroll
        for (int b = 0; b < 8; b++)
#pragma unroll
            for (int c = 0; c < 4; c++) acc[a][b][c] = 0.f;

    gemm_mainloop(A, DDIM, 4, W, smem, acc);

    float* ep = reinterpret_cast<float*>(smem + OUT_STAGE);
    const int tid = threadIdx.x, lane = tid & 31, wid = tid >> 5;
    const int wm = (wid & 3) * 32, wn = (wid >> 2) * 64;
#pragma unroll
    for (int mt = 0; mt < 2; mt++) {
        int r0 = wm + mt * 16 + (lane >> 2);
#pragma unroll
        for (int nt = 0; nt < 8; nt++) {
            int ccol = wn + nt * 8 + (lane & 3) * 2;
            *reinterpret_cast<float2*>(&ep[r0 * EPS + ccol]) =
                make_float2(acc[mt][nt][0], acc[mt][nt][1]);
            *reinterpret_cast<float2*>(&ep[(r0 + 8) * EPS + ccol]) =
                make_float2(acc[mt][nt][2], acc[mt][nt][3]);
        }
    }
    __syncthreads();

#pragma unroll
    for (int i = 0; i < 16; i++) {
        int idx = tid + 256 * i;
        int row = idx >> 5, c4 = (idx & 31) * 4;
        float4 v = *reinterpret_cast<const float4*>(&ep[row * EPS + c4]);
        float4 bv = *reinterpret_cast<const float4*>(&bias[c4]);
        float4 rv = *reinterpret_cast<const float4*>(&resid[(size_t)row * CDIM + c4]);
        v.x += bv.x + rv.x; v.y += bv.y + rv.y;
        v.z += bv.z + rv.z; v.w += bv.w + rv.w;
        *reinterpret_cast<float4*>(&outp[(size_t)row * CDIM + c4]) = v;
    }
}

// ------------------------------- launch -------------------------------
extern "C" void kernel_launch(void* const* d_in, const int* in_sizes, int n_in,
                              void* d_out, int out_size) {
    const float* x0   = (const float*)d_in[0];
    const float* x1   = (const float*)d_in[1];
    const float* g_w  = (const float*)d_in[2];
    const float* g_b  = (const float*)d_in[3];
    const float* th_w = (const float*)d_in[4];
    const float* th_b = (const float*)d_in[5];
    const float* ph_w = (const float*)d_in[6];
    const float* ph_b = (const float*)d_in[7];
    const float* W_w  = (const float*)d_in[8];
    const float* W_b  = (const float*)d_in[9];
    float* out = (float*)d_out;

    void* p_done = nullptr;
    cudaGetSymbolAddress(&p_done, d_done);
    cudaFuncSetAttribute(out_gemm, cudaFuncAttributeMaxDynamicSharedMemorySize, OUT_SMEM);

    cudaMemsetAsync(p_done, 0, 128 * sizeof(int), 0);

    split4_kernel<<<dim3(32, 4), 256>>>(g_w, th_w, ph_w, W_w);

    fused_proj_attn<<<2 * NSM, 256, GSMEM>>>(x0, x1, g_b, th_b, ph_b);

    out_gemm<<<dim3(8, BDIM / 128), 256, OUT_SMEM>>>(W_b, x0, out);
}

// round 15
// speedup vs baseline: 1.0654x; 1.0654x over previous
#include <cuda_runtime.h>
#include <cuda_fp16.h>
#include <cstdint>

#define BDIM 16384
#define CDIM 1024
#define DDIM 128
#define LOG2E 1.4426950408889634f

// ------------------------------- scratch -------------------------------
__device__ float s_theta[BDIM * DDIM];
__device__ float s_phi[BDIM * DDIM];
__device__ float s_g[BDIM * DDIM];
__device__ float s_y[BDIM * DDIM];

__device__ __half s_gw[DDIM * CDIM];
__device__ __half s_thw[DDIM * CDIM];
__device__ __half s_phw[DDIM * CDIM];
__device__ __half s_Ww[CDIM * DDIM];

// ------------------------------- helpers -------------------------------
__device__ __forceinline__ unsigned pkh(__half a, __half b) {
    return (unsigned)__half_as_ushort(a) | ((unsigned)__half_as_ushort(b) << 16);
}
__device__ __forceinline__ void ldsm4(uint32_t* r, uint32_t addr) {
    asm volatile("ldmatrix.sync.aligned.m8n8.x4.shared.b16 {%0,%1,%2,%3}, [%4];"
                 : "=r"(r[0]), "=r"(r[1]), "=r"(r[2]), "=r"(r[3]) : "r"(addr));
}
__device__ __forceinline__ void mma16816(float* c, const uint32_t* a, uint32_t b0, uint32_t b1) {
    asm volatile(
        "mma.sync.aligned.m16n8k16.row.col.f32.f16.f16.f32 "
        "{%0,%1,%2,%3}, {%4,%5,%6,%7}, {%8,%9}, {%0,%1,%2,%3};"
        : "+f"(c[0]), "+f"(c[1]), "+f"(c[2]), "+f"(c[3])
        : "r"(a[0]), "r"(a[1]), "r"(a[2]), "r"(a[3]), "r"(b0), "r"(b1));
}
// fp16-accumulate variant: D/C are 2 regs of packed half2
__device__ __forceinline__ void mma16816h(uint32_t* c, const uint32_t* a, uint32_t b0, uint32_t b1) {
    asm volatile(
        "mma.sync.aligned.m16n8k16.row.col.f16.f16.f16.f16 "
        "{%0,%1}, {%2,%3,%4,%5}, {%6,%7}, {%0,%1};"
        : "+r"(c[0]), "+r"(c[1])
        : "r"(a[0]), "r"(a[1]), "r"(a[2]), "r"(a[3]), "r"(b0), "r"(b1));
}
__device__ __forceinline__ void cp16(uint32_t dst, const void* src) {
    asm volatile("cp.async.cg.shared.global [%0], [%1], 16;" :: "r"(dst), "l"(src));
}
#define CP_COMMIT() asm volatile("cp.async.commit_group;")
#define CP_WAIT1()  asm volatile("cp.async.wait_group 1;")
__device__ __forceinline__ float ex2f(float x) {
    float r; asm("ex2.approx.ftz.f32 %0, %1;" : "=f"(r) : "f"(x)); return r;
}

// ---------------- fused weight fp16 convert (4 weights, one launch) ----------------
__global__ void split4_kernel(const float* __restrict__ w0, const float* __restrict__ w1,
                              const float* __restrict__ w2, const float* __restrict__ w3) {
    int wsel = blockIdx.y;
    const float* in = wsel == 0 ? w0 : wsel == 1 ? w1 : wsel == 2 ? w2 : w3;
    __half* hp = wsel == 0 ? s_gw : wsel == 1 ? s_thw : wsel == 2 ? s_phw : s_Ww;
    const int n4 = DDIM * CDIM / 4;
    const float4* in4 = reinterpret_cast<const float4*>(in);
    uint2* h2 = reinterpret_cast<uint2*>(hp);
    for (int i = blockIdx.x * blockDim.x + threadIdx.x; i < n4; i += gridDim.x * blockDim.x) {
        float4 v = in4[i];
        h2[i] = make_uint2(pkh(__float2half_rn(v.x), __float2half_rn(v.y)),
                           pkh(__float2half_rn(v.z), __float2half_rn(v.w)));
    }
}

// ---------------- shared tiling constants ----------------
#define SAP 40
#define oW 10240u
#define GSMEM 30720

// ---------------- fp32-acc mainloop (proven; used by out_gemm) ----------------
__device__ __forceinline__ void gemm_mainloop(
    const float* __restrict__ A, int K, int NC,
    const __half* __restrict__ W, unsigned char* smem, float acc[2][8][4]) {
    const int tid = threadIdx.x, lane = tid & 31, wid = tid >> 5;
    const int wm = (wid & 3) * 32, wn = (wid >> 2) * 64;
    const uint32_t sbase = (uint32_t)__cvta_generic_to_shared(smem);

    float4 stage[4];
    {
#pragma unroll
        for (int i = 0; i < 4; i++) {
            int q = tid + 256 * i;
            stage[i] = *reinterpret_cast<const float4*>(
                &A[(size_t)(q >> 3) * K + (q & 7) * 4]);
        }
#pragma unroll
        for (int i = 0; i < 2; i++) {
            int q = tid + 256 * i;
            int r = q >> 2, cc = q & 3;
            cp16(sbase + oW + (uint32_t)(r * SAP + cc * 8) * 2,
                 W + (size_t)r * K + cc * 8);
        }
        CP_COMMIT();
    }

    for (int c = 0; c < NC; c++) {
#pragma unroll
        for (int i = 0; i < 4; i++) {
            int q = tid + 256 * i;
            int r = q >> 3, c4 = q & 7;
            float4 v = stage[i];
            *reinterpret_cast<uint2*>(smem + (size_t)(r * SAP + c4 * 4) * 2) =
                make_uint2(pkh(__float2half_rn(v.x), __float2half_rn(v.y)),
                           pkh(__float2half_rn(v.z), __float2half_rn(v.w)));
        }
        if (c + 1 < NC) {
            int kk = (c + 1) * 32, buf = (c + 1) & 1;
#pragma unroll
            for (int i = 0; i < 4; i++) {
                int q = tid + 256 * i;
                stage[i] = *reinterpret_cast<const float4*>(
                    &A[(size_t)(q >> 3) * K + kk + (q & 7) * 4]);
            }
#pragma unroll
            for (int i = 0; i < 2; i++) {
                int q = tid + 256 * i;
                int r = q >> 2, cc = q & 3;
                cp16(sbase + oW + (uint32_t)buf * 10240u + (uint32_t)(r * SAP + cc * 8) * 2,
                     W + (size_t)r * K + kk + cc * 8);
            }
        }
        CP_COMMIT();
        CP_WAIT1();
        __syncthreads();

        const uint32_t wb = sbase + oW + (uint32_t)(c & 1) * 10240u;
#pragma unroll
        for (int ks = 0; ks < 2; ks++) {
            uint32_t ah[2][4], wf[4][4];
#pragma unroll
            for (int mt = 0; mt < 2; mt++) {
                uint32_t aoff = (uint32_t)((wm + mt * 16 + (lane & 15)) * SAP +
                                           ks * 16 + (lane >> 4) * 8) * 2;
                ldsm4(ah[mt], sbase + aoff);
            }
#pragma unroll
            for (int p = 0; p < 4; p++) {
                uint32_t woff = (uint32_t)((wn + p * 16 + (lane & 7) + ((lane >> 4) & 1) * 8) * SAP +
                                           ks * 16 + ((lane >> 3) & 1) * 8) * 2;
                ldsm4(wf[p], wb + woff);
            }
#pragma unroll
            for (int mt = 0; mt < 2; mt++)
#pragma unroll
                for (int p = 0; p < 4; p++) {
                    mma16816(acc[mt][2 * p], ah[mt], wf[p][0], wf[p][1]);
                    mma16816(acc[mt][2 * p + 1], ah[mt], wf[p][2], wf[p][3]);
                }
        }
        __syncthreads();
    }
}

// ---------------- fp16-acc mainloop (proj): fp16 C per chunk, fp32 dump ----------------
__device__ __forceinline__ void gemm_mainloop_h(
    const float* __restrict__ A, int K, int NC,
    const __half* __restrict__ W, unsigned char* smem, float acc[2][8][4]) {
    const int tid = threadIdx.x, lane = tid & 31, wid = tid >> 5;
    const int wm = (wid & 3) * 32, wn = (wid >> 2) * 64;
    const uint32_t sbase = (uint32_t)__cvta_generic_to_shared(smem);

    float4 stage[4];
    {
#pragma unroll
        for (int i = 0; i < 4; i++) {
            int q = tid + 256 * i;
            stage[i] = *reinterpret_cast<const float4*>(
                &A[(size_t)(q >> 3) * K + (q & 7) * 4]);
        }
#pragma unroll
        for (int i = 0; i < 2; i++) {
            int q = tid + 256 * i;
            int r = q >> 2, cc = q & 3;
            cp16(sbase + oW + (uint32_t)(r * SAP + cc * 8) * 2,
                 W + (size_t)r * K + cc * 8);
        }
        CP_COMMIT();
    }

    for (int c = 0; c < NC; c++) {
#pragma unroll
        for (int i = 0; i < 4; i++) {
            int q = tid + 256 * i;
            int r = q >> 3, c4 = q & 7;
            float4 v = stage[i];
            *reinterpret_cast<uint2*>(smem + (size_t)(r * SAP + c4 * 4) * 2) =
                make_uint2(pkh(__float2half_rn(v.x), __float2half_rn(v.y)),
                           pkh(__float2half_rn(v.z), __float2half_rn(v.w)));
        }
        if (c + 1 < NC) {
            int kk = (c + 1) * 32, buf = (c + 1) & 1;
#pragma unroll
            for (int i = 0; i < 4; i++) {
                int q = tid + 256 * i;
                stage[i] = *reinterpret_cast<const float4*>(
                    &A[(size_t)(q >> 3) * K + kk + (q & 7) * 4]);
            }
#pragma unroll
            for (int i = 0; i < 2; i++) {
                int q = tid + 256 * i;
                int r = q >> 2, cc = q & 3;
                cp16(sbase + oW + (uint32_t)buf * 10240u + (uint32_t)(r * SAP + cc * 8) * 2,
                     W + (size_t)r * K + kk + cc * 8);
            }
        }
        CP_COMMIT();
        CP_WAIT1();
        __syncthreads();

        // fresh fp16 accumulators for this 32-k chunk
        uint32_t hacc[2][8][2];
#pragma unroll
        for (int a = 0; a < 2; a++)
#pragma unroll
            for (int b = 0; b < 8; b++) { hacc[a][b][0] = 0u; hacc[a][b][1] = 0u; }

        const uint32_t wb = sbase + oW + (uint32_t)(c & 1) * 10240u;
#pragma unroll
        for (int ks = 0; ks < 2; ks++) {
            uint32_t ah[2][4], wf[4][4];
#pragma unroll
            for (int mt = 0; mt < 2; mt++) {
                uint32_t aoff = (uint32_t)((wm + mt * 16 + (lane & 15)) * SAP +
                                           ks * 16 + (lane >> 4) * 8) * 2;
                ldsm4(ah[mt], sbase + aoff);
            }
#pragma unroll
            for (int p = 0; p < 4; p++) {
                uint32_t woff = (uint32_t)((wn + p * 16 + (lane & 7) + ((lane >> 4) & 1) * 8) * SAP +
                                           ks * 16 + ((lane >> 3) & 1) * 8) * 2;
                ldsm4(wf[p], wb + woff);
            }
#pragma unroll
            for (int mt = 0; mt < 2; mt++)
#pragma unroll
                for (int p = 0; p < 4; p++) {
                    mma16816h(hacc[mt][2 * p], ah[mt], wf[p][0], wf[p][1]);
                    mma16816h(hacc[mt][2 * p + 1], ah[mt], wf[p][2], wf[p][3]);
                }
        }
        // dump chunk partials into fp32 accumulators
#pragma unroll
        for (int mt = 0; mt < 2; mt++)
#pragma unroll
            for (int nt = 0; nt < 8; nt++) {
                __half2 h0 = *reinterpret_cast<__half2*>(&hacc[mt][nt][0]);
                __half2 h1 = *reinterpret_cast<__half2*>(&hacc[mt][nt][1]);
                float2 f0 = __half22float2(h0);
                float2 f1 = __half22float2(h1);
                acc[mt][nt][0] += f0.x; acc[mt][nt][1] += f0.y;
                acc[mt][nt][2] += f1.x; acc[mt][nt][3] += f1.y;
            }
        __syncthreads();
    }
}

// grid (3, 128): x = {g, theta, phi}, y = row tile. fp16-acc HMMA path.
__global__ void __launch_bounds__(256)
proj_gemm(const float* __restrict__ x0, const float* __restrict__ x1,
          const float* __restrict__ gb, const float* __restrict__ thb,
          const float* __restrict__ phb) {
    extern __shared__ unsigned char smem[];
    int bz = blockIdx.x;
    size_t bm = (size_t)blockIdx.y * 128;
    const float* A = (bz == 0 ? x0 : x1) + bm * CDIM;
    const __half* W = bz == 0 ? s_gw : bz == 1 ? s_thw : s_phw;
    const float* bias = bz == 0 ? gb : bz == 1 ? thb : phb;
    float* out = (bz == 0 ? s_g : bz == 1 ? s_theta : s_phi) + bm * DDIM;

    float acc[2][8][4];
#pragma unroll
    for (int a = 0; a < 2; a++)
#pragma unroll
        for (int b = 0; b < 8; b++)
#pragma unroll
            for (int c = 0; c < 4; c++) acc[a][b][c] = 0.f;

    gemm_mainloop_h(A, CDIM, 32, W, smem, acc);

    const int lane = threadIdx.x & 31, wid = threadIdx.x >> 5;
    const int wm = (wid & 3) * 32, wn = (wid >> 2) * 64;
#pragma unroll
    for (int mt = 0; mt < 2; mt++) {
        int r0 = wm + mt * 16 + (lane >> 2);
#pragma unroll
        for (int nt = 0; nt < 8; nt++) {
            int ccol = wn + nt * 8 + (lane & 3) * 2;
            float2 v0 = make_float2(acc[mt][nt][0] + bias[ccol], acc[mt][nt][1] + bias[ccol + 1]);
            float2 v1 = make_float2(acc[mt][nt][2] + bias[ccol], acc[mt][nt][3] + bias[ccol + 1]);
            *reinterpret_cast<float2*>(&out[(size_t)r0 * DDIM + ccol]) = v0;
            *reinterpret_cast<float2*>(&out[(size_t)(r0 + 8) * DDIM + ccol]) = v1;
        }
    }
}

// ---------------- out GEMM (R10-proven: smem-staged coalesced epilogue, 2 CTAs/SM) ----------------
#define EPS 132
#define OUT_STAGE (20480u)
#define OUT_SMEM (20480 + 128 * EPS * 4)

__global__ void __launch_bounds__(256, 2)
out_gemm(const float* __restrict__ Wb, const float* __restrict__ x0, float* __restrict__ out) {
    extern __shared__ unsigned char smem[];
    size_t n0 = (size_t)blockIdx.x * 128;
    size_t bm = (size_t)blockIdx.y * 128;
    const float* A = s_y + bm * DDIM;
    const __half* W = s_Ww + n0 * DDIM;
    const float* resid = x0 + bm * CDIM + n0;
    float* outp = out + bm * CDIM + n0;
    const float* bias = Wb + n0;

    float acc[2][8][4];
#pragma unroll
    for (int a = 0; a < 2; a++)
#pragma unroll
        for (int b = 0; b < 8; b++)
#pragma unroll
            for (int c = 0; c < 4; c++) acc[a][b][c] = 0.f;

    gemm_mainloop(A, DDIM, 4, W, smem, acc);

    float* ep = reinterpret_cast<float*>(smem + OUT_STAGE);
    const int tid = threadIdx.x, lane = tid & 31, wid = tid >> 5;
    const int wm = (wid & 3) * 32, wn = (wid >> 2) * 64;
#pragma unroll
    for (int mt = 0; mt < 2; mt++) {
        int r0 = wm + mt * 16 + (lane >> 2);
#pragma unroll
        for (int nt = 0; nt < 8; nt++) {
            int ccol = wn + nt * 8 + (lane & 3) * 2;
            *reinterpret_cast<float2*>(&ep[r0 * EPS + ccol]) =
                make_float2(acc[mt][nt][0], acc[mt][nt][1]);
            *reinterpret_cast<float2*>(&ep[(r0 + 8) * EPS + ccol]) =
                make_float2(acc[mt][nt][2], acc[mt][nt][3]);
        }
    }
    __syncthreads();

#pragma unroll
    for (int i = 0; i < 16; i++) {
        int idx = tid + 256 * i;
        int row = idx >> 5, c4 = (idx & 31) * 4;
        float4 v = *reinterpret_cast<const float4*>(&ep[row * EPS + c4]);
        float4 bv = *reinterpret_cast<const float4*>(&bias[c4]);
        float4 rv = *reinterpret_cast<const float4*>(&resid[(size_t)row * CDIM + c4]);
        v.x += bv.x + rv.x; v.y += bv.y + rv.y;
        v.z += bv.z + rv.z; v.w += bv.w + rv.w;
        *reinterpret_cast<float4*>(&outp[(size_t)row * CDIM + c4]) = v;
    }
}

// ---------------- rank-1 softmax attention (R10-proven pure ex2f) ----------------
__global__ void __launch_bounds__(512)
attn16_kernel() {
    __shared__ float sth[16 * 128], sg[16 * 128], sph[16 * 128];
    const int tid = threadIdx.x;
    const size_t base = (size_t)blockIdx.x * 16 * 128;
    reinterpret_cast<float4*>(sth)[tid] = reinterpret_cast<const float4*>(s_theta + base)[tid];
    reinterpret_cast<float4*>(sg)[tid]  = reinterpret_cast<const float4*>(s_g + base)[tid];
    reinterpret_cast<float4*>(sph)[tid] = reinterpret_cast<const float4*>(s_phi + base)[tid];
    __syncwarp();

    const int w = tid >> 5, l = tid & 31;
    const float* th = sth + w * 128;
    const float* gg = sg + w * 128;
    const float* ph = sph + w * 128;

    float a0 = th[l], a1 = th[l + 32], a2 = th[l + 64], a3 = th[l + 96];
    float mx = fmaxf(fmaxf(a0, a1), fmaxf(a2, a3));
    float mn = fminf(fminf(a0, a1), fminf(a2, a3));
#pragma unroll
    for (int off = 16; off >= 1; off >>= 1) {
        mx = fmaxf(mx, __shfl_xor_sync(0xffffffffu, mx, off));
        mn = fminf(mn, __shfl_xor_sync(0xffffffffu, mn, off));
    }
    float sc[4], m2n[4], num[4], den[4];
#pragma unroll
    for (int q = 0; q < 4; q++) {
        sc[q] = ph[l + 32 * q] * LOG2E;
        m2n[q] = -sc[q] * (sc[q] >= 0.f ? mx : mn);
        num[q] = 0.f; den[q] = 0.f;
    }
#pragma unroll 8
    for (int j = 0; j < 128; j += 4) {
        float4 tv = *reinterpret_cast<const float4*>(&th[j]);
        float4 gv = *reinterpret_cast<const float4*>(&gg[j]);
        float t_[4] = {tv.x, tv.y, tv.z, tv.w};
        float g_[4] = {gv.x, gv.y, gv.z, gv.w};
#pragma unroll
        for (int e = 0; e < 4; e++) {
#pragma unroll
            for (int q = 0; q < 4; q++) {
                float ex = ex2f(fmaf(sc[q], t_[e], m2n[q]));
                num[q] = fmaf(ex, g_[e], num[q]);
                den[q] += ex;
            }
        }
    }
#pragma unroll
    for (int q = 0; q < 4; q++)
        s_y[base + (size_t)w * 128 + l + 32 * q] = num[q] / den[q];
}

// ------------------------------- launch -------------------------------
extern "C" void kernel_launch(void* const* d_in, const int* in_sizes, int n_in,
                              void* d_out, int out_size) {
    const float* x0   = (const float*)d_in[0];
    const float* x1   = (const float*)d_in[1];
    const float* g_w  = (const float*)d_in[2];
    const float* g_b  = (const float*)d_in[3];
    const float* th_w = (const float*)d_in[4];
    const float* th_b = (const float*)d_in[5];
    const float* ph_w = (const float*)d_in[6];
    const float* ph_b = (const float*)d_in[7];
    const float* W_w  = (const float*)d_in[8];
    const float* W_b  = (const float*)d_in[9];
    float* out = (float*)d_out;

    cudaFuncSetAttribute(out_gemm, cudaFuncAttributeMaxDynamicSharedMemorySize, OUT_SMEM);

    split4_kernel<<<dim3(32, 4), 256>>>(g_w, th_w, ph_w, W_w);

    proj_gemm<<<dim3(3, BDIM / 128), 256, GSMEM>>>(x0, x1, g_b, th_b, ph_b);

    attn16_kernel<<<BDIM / 16, 512>>>();

    out_gemm<<<dim3(8, BDIM / 128), 256, OUT_SMEM>>>(W_b, x0, out);
}

// round 16
// speedup vs baseline: 1.2896x; 1.2105x over previous
#include <cuda_runtime.h>
#include <cuda_fp16.h>
#include <cstdint>

#define BDIM 16384
#define CDIM 1024
#define DDIM 128
#define LOG2E 1.4426950408889634f

// ------------------------------- scratch -------------------------------
__device__ float s_theta[BDIM * DDIM];
__device__ float s_phi[BDIM * DDIM];
__device__ float s_g[BDIM * DDIM];
__device__ float s_y[BDIM * DDIM];

__device__ __half s_gw[DDIM * CDIM];
__device__ __half s_thw[DDIM * CDIM];
__device__ __half s_phw[DDIM * CDIM];
__device__ __half s_Ww[CDIM * DDIM];

// ------------------------------- helpers -------------------------------
__device__ __forceinline__ unsigned pkh(__half a, __half b) {
    return (unsigned)__half_as_ushort(a) | ((unsigned)__half_as_ushort(b) << 16);
}
__device__ __forceinline__ void ldsm4(uint32_t* r, uint32_t addr) {
    asm volatile("ldmatrix.sync.aligned.m8n8.x4.shared.b16 {%0,%1,%2,%3}, [%4];"
                 : "=r"(r[0]), "=r"(r[1]), "=r"(r[2]), "=r"(r[3]) : "r"(addr));
}
__device__ __forceinline__ void mma16816(float* c, const uint32_t* a, uint32_t b0, uint32_t b1) {
    asm volatile(
        "mma.sync.aligned.m16n8k16.row.col.f32.f16.f16.f32 "
        "{%0,%1,%2,%3}, {%4,%5,%6,%7}, {%8,%9}, {%0,%1,%2,%3};"
        : "+f"(c[0]), "+f"(c[1]), "+f"(c[2]), "+f"(c[3])
        : "r"(a[0]), "r"(a[1]), "r"(a[2]), "r"(a[3]), "r"(b0), "r"(b1));
}
__device__ __forceinline__ void cp16(uint32_t dst, const void* src) {
    asm volatile("cp.async.cg.shared.global [%0], [%1], 16;" :: "r"(dst), "l"(src));
}
#define CP_COMMIT() asm volatile("cp.async.commit_group;")
#define CP_WAIT1()  asm volatile("cp.async.wait_group 1;")
#define CP_WAIT0()  asm volatile("cp.async.wait_group 0;")
__device__ __forceinline__ float ex2f(float x) {
    float r; asm("ex2.approx.ftz.f32 %0, %1;" : "=f"(r) : "f"(x)); return r;
}

// ---------------- fused weight fp16 convert (4 weights, one launch) ----------------
__global__ void split4_kernel(const float* __restrict__ w0, const float* __restrict__ w1,
                              const float* __restrict__ w2, const float* __restrict__ w3) {
    int wsel = blockIdx.y;
    const float* in = wsel == 0 ? w0 : wsel == 1 ? w1 : wsel == 2 ? w2 : w3;
    __half* hp = wsel == 0 ? s_gw : wsel == 1 ? s_thw : wsel == 2 ? s_phw : s_Ww;
    const int n4 = DDIM * CDIM / 4;
    const float4* in4 = reinterpret_cast<const float4*>(in);
    uint2* h2 = reinterpret_cast<uint2*>(hp);
    for (int i = blockIdx.x * blockDim.x + threadIdx.x; i < n4; i += gridDim.x * blockDim.x) {
        float4 v = in4[i];
        h2[i] = make_uint2(pkh(__float2half_rn(v.x), __float2half_rn(v.y)),
                           pkh(__float2half_rn(v.z), __float2half_rn(v.w)));
    }
}

// ---------------- shared tiling constants ----------------
#define SAP 40
#define oW 10240u
#define GSMEM 30720
// proj variant: A double buffer [0,20480), W double buffer [20480,40960)
#define oWP 20480u
#define PSMEM 40960

// ---------------- fp32-acc mainloop (R10-proven; used by out_gemm) ----------------
__device__ __forceinline__ void gemm_mainloop(
    const float* __restrict__ A, int K, int NC,
    const __half* __restrict__ W, unsigned char* smem, float acc[2][8][4]) {
    const int tid = threadIdx.x, lane = tid & 31, wid = tid >> 5;
    const int wm = (wid & 3) * 32, wn = (wid >> 2) * 64;
    const uint32_t sbase = (uint32_t)__cvta_generic_to_shared(smem);

    float4 stage[4];
    {
#pragma unroll
        for (int i = 0; i < 4; i++) {
            int q = tid + 256 * i;
            stage[i] = *reinterpret_cast<const float4*>(
                &A[(size_t)(q >> 3) * K + (q & 7) * 4]);
        }
#pragma unroll
        for (int i = 0; i < 2; i++) {
            int q = tid + 256 * i;
            int r = q >> 2, cc = q & 3;
            cp16(sbase + oW + (uint32_t)(r * SAP + cc * 8) * 2,
                 W + (size_t)r * K + cc * 8);
        }
        CP_COMMIT();
    }

    for (int c = 0; c < NC; c++) {
#pragma unroll
        for (int i = 0; i < 4; i++) {
            int q = tid + 256 * i;
            int r = q >> 3, c4 = q & 7;
            float4 v = stage[i];
            *reinterpret_cast<uint2*>(smem + (size_t)(r * SAP + c4 * 4) * 2) =
                make_uint2(pkh(__float2half_rn(v.x), __float2half_rn(v.y)),
                           pkh(__float2half_rn(v.z), __float2half_rn(v.w)));
        }
        if (c + 1 < NC) {
            int kk = (c + 1) * 32, buf = (c + 1) & 1;
#pragma unroll
            for (int i = 0; i < 4; i++) {
                int q = tid + 256 * i;
                stage[i] = *reinterpret_cast<const float4*>(
                    &A[(size_t)(q >> 3) * K + kk + (q & 7) * 4]);
            }
#pragma unroll
            for (int i = 0; i < 2; i++) {
                int q = tid + 256 * i;
                int r = q >> 2, cc = q & 3;
                cp16(sbase + oW + (uint32_t)buf * 10240u + (uint32_t)(r * SAP + cc * 8) * 2,
                     W + (size_t)r * K + kk + cc * 8);
            }
        }
        CP_COMMIT();
        CP_WAIT1();
        __syncthreads();

        const uint32_t wb = sbase + oW + (uint32_t)(c & 1) * 10240u;
#pragma unroll
        for (int ks = 0; ks < 2; ks++) {
            uint32_t ah[2][4], wf[4][4];
#pragma unroll
            for (int mt = 0; mt < 2; mt++) {
                uint32_t aoff = (uint32_t)((wm + mt * 16 + (lane & 15)) * SAP +
                                           ks * 16 + (lane >> 4) * 8) * 2;
                ldsm4(ah[mt], sbase + aoff);
            }
#pragma unroll
            for (int p = 0; p < 4; p++) {
                uint32_t woff = (uint32_t)((wn + p * 16 + (lane & 7) + ((lane >> 4) & 1) * 8) * SAP +
                                           ks * 16 + ((lane >> 3) & 1) * 8) * 2;
                ldsm4(wf[p], wb + woff);
            }
#pragma unroll
            for (int mt = 0; mt < 2; mt++)
#pragma unroll
                for (int p = 0; p < 4; p++) {
                    mma16816(acc[mt][2 * p], ah[mt], wf[p][0], wf[p][1]);
                    mma16816(acc[mt][2 * p + 1], ah[mt], wf[p][2], wf[p][3]);
                }
        }
        __syncthreads();
    }
}

// ---------------- proj mainloop: A double-buffered, ONE sync per chunk ----------------
// Order per chunk c: STS A(c) -> LDG-stage A(c+1) -> wait_group 0 (W(c) done)
// -> __syncthreads (all warps past MMA(c-1)) -> cp W(c+1) -> MMA(c).
// Hazard check: STS A(c) writes buf c&1, last read by MMA(c-2), all warps past
// sync(c-1) which follows their MMA(c-2). cp W(c+1) writes W buf (c+1)&1, last
// read by MMA(c-1); issued only after sync(c). Correct by barrier ordering.
__device__ __forceinline__ void gemm_mainloop_p(
    const float* __restrict__ A, int K, int NC,
    const __half* __restrict__ W, unsigned char* smem, float acc[2][8][4]) {
    const int tid = threadIdx.x, lane = tid & 31, wid = tid >> 5;
    const int wm = (wid & 3) * 32, wn = (wid >> 2) * 64;
    const uint32_t sbase = (uint32_t)__cvta_generic_to_shared(smem);

    float4 stage[4];
    {
#pragma unroll
        for (int i = 0; i < 4; i++) {
            int q = tid + 256 * i;
            stage[i] = *reinterpret_cast<const float4*>(
                &A[(size_t)(q >> 3) * K + (q & 7) * 4]);
        }
#pragma unroll
        for (int i = 0; i < 2; i++) {
            int q = tid + 256 * i;
            int r = q >> 2, cc = q & 3;
            cp16(sbase + oWP + (uint32_t)(r * SAP + cc * 8) * 2,
                 W + (size_t)r * K + cc * 8);
        }
        CP_COMMIT();
    }

    for (int c = 0; c < NC; c++) {
        const uint32_t abuf = (uint32_t)(c & 1) * 10240u;
        // STS A(c) into its buffer
#pragma unroll
        for (int i = 0; i < 4; i++) {
            int q = tid + 256 * i;
            int r = q >> 3, c4 = q & 7;
            float4 v = stage[i];
            *reinterpret_cast<uint2*>(smem + abuf + (size_t)(r * SAP + c4 * 4) * 2) =
                make_uint2(pkh(__float2half_rn(v.x), __float2half_rn(v.y)),
                           pkh(__float2half_rn(v.z), __float2half_rn(v.w)));
        }
        // stage A(c+1) into regs (no smem hazard)
        if (c + 1 < NC) {
            int kk = (c + 1) * 32;
#pragma unroll
            for (int i = 0; i < 4; i++) {
                int q = tid + 256 * i;
                stage[i] = *reinterpret_cast<const float4*>(
                    &A[(size_t)(q >> 3) * K + kk + (q & 7) * 4]);
            }
        }
        CP_WAIT0();        // W(c) resident (committed one chunk ago)
        __syncthreads();   // all warps finished MMA(c-1); STS A(c) visible
        // cp W(c+1) -> other W buffer (safe: nobody reads it anymore)
        if (c + 1 < NC) {
            int kk = (c + 1) * 32;
            uint32_t wdst = sbase + oWP + (uint32_t)((c + 1) & 1) * 10240u;
#pragma unroll
            for (int i = 0; i < 2; i++) {
                int q = tid + 256 * i;
                int r = q >> 2, cc = q & 3;
                cp16(wdst + (uint32_t)(r * SAP + cc * 8) * 2,
                     W + (size_t)r * K + kk + cc * 8);
            }
            CP_COMMIT();
        }
        // MMA on A buf(c&1), W buf(c&1)
        const uint32_t wb = sbase + oWP + (uint32_t)(c & 1) * 10240u;
#pragma unroll
        for (int ks = 0; ks < 2; ks++) {
            uint32_t ah[2][4], wf[4][4];
#pragma unroll
            for (int mt = 0; mt < 2; mt++) {
                uint32_t aoff = (uint32_t)((wm + mt * 16 + (lane & 15)) * SAP +
                                           ks * 16 + (lane >> 4) * 8) * 2;
                ldsm4(ah[mt], sbase + abuf + aoff);
            }
#pragma unroll
            for (int p = 0; p < 4; p++) {
                uint32_t woff = (uint32_t)((wn + p * 16 + (lane & 7) + ((lane >> 4) & 1) * 8) * SAP +
                                           ks * 16 + ((lane >> 3) & 1) * 8) * 2;
                ldsm4(wf[p], wb + woff);
            }
#pragma unroll
            for (int mt = 0; mt < 2; mt++)
#pragma unroll
                for (int p = 0; p < 4; p++) {
                    mma16816(acc[mt][2 * p], ah[mt], wf[p][0], wf[p][1]);
                    mma16816(acc[mt][2 * p + 1], ah[mt], wf[p][2], wf[p][3]);
                }
        }
    }
}

// grid (3, 128): x = {g, theta, phi}, y = row tile.
__global__ void __launch_bounds__(256, 2)
proj_gemm(const float* __restrict__ x0, const float* __restrict__ x1,
          const float* __restrict__ gb, const float* __restrict__ thb,
          const float* __restrict__ phb) {
    extern __shared__ unsigned char smem[];
    int bz = blockIdx.x;
    size_t bm = (size_t)blockIdx.y * 128;
    const float* A = (bz == 0 ? x0 : x1) + bm * CDIM;
    const __half* W = bz == 0 ? s_gw : bz == 1 ? s_thw : s_phw;
    const float* bias = bz == 0 ? gb : bz == 1 ? thb : phb;
    float* out = (bz == 0 ? s_g : bz == 1 ? s_theta : s_phi) + bm * DDIM;

    float acc[2][8][4];
#pragma unroll
    for (int a = 0; a < 2; a++)
#pragma unroll
        for (int b = 0; b < 8; b++)
#pragma unroll
            for (int c = 0; c < 4; c++) acc[a][b][c] = 0.f;

    gemm_mainloop_p(A, CDIM, 32, W, smem, acc);

    const int lane = threadIdx.x & 31, wid = threadIdx.x >> 5;
    const int wm = (wid & 3) * 32, wn = (wid >> 2) * 64;
#pragma unroll
    for (int mt = 0; mt < 2; mt++) {
        int r0 = wm + mt * 16 + (lane >> 2);
#pragma unroll
        for (int nt = 0; nt < 8; nt++) {
            int ccol = wn + nt * 8 + (lane & 3) * 2;
            float2 v0 = make_float2(acc[mt][nt][0] + bias[ccol], acc[mt][nt][1] + bias[ccol + 1]);
            float2 v1 = make_float2(acc[mt][nt][2] + bias[ccol], acc[mt][nt][3] + bias[ccol + 1]);
            *reinterpret_cast<float2*>(&out[(size_t)r0 * DDIM + ccol]) = v0;
            *reinterpret_cast<float2*>(&out[(size_t)(r0 + 8) * DDIM + ccol]) = v1;
        }
    }
}

// ---------------- out GEMM (R10-proven: smem-staged coalesced epilogue, 2 CTAs/SM) ----------------
#define EPS 132
#define OUT_STAGE (20480u)
#define OUT_SMEM (20480 + 128 * EPS * 4)

__global__ void __launch_bounds__(256, 2)
out_gemm(const float* __restrict__ Wb, const float* __restrict__ x0, float* __restrict__ out) {
    extern __shared__ unsigned char smem[];
    size_t n0 = (size_t)blockIdx.x * 128;
    size_t bm = (size_t)blockIdx.y * 128;
    const float* A = s_y + bm * DDIM;
    const __half* W = s_Ww + n0 * DDIM;
    const float* resid = x0 + bm * CDIM + n0;
    float* outp = out + bm * CDIM + n0;
    const float* bias = Wb + n0;

    float acc[2][8][4];
#pragma unroll
    for (int a = 0; a < 2; a++)
#pragma unroll
        for (int b = 0; b < 8; b++)
#pragma unroll
            for (int c = 0; c < 4; c++) acc[a][b][c] = 0.f;

    gemm_mainloop(A, DDIM, 4, W, smem, acc);

    float* ep = reinterpret_cast<float*>(smem + OUT_STAGE);
    const int tid = threadIdx.x, lane = tid & 31, wid = tid >> 5;
    const int wm = (wid & 3) * 32, wn = (wid >> 2) * 64;
#pragma unroll
    for (int mt = 0; mt < 2; mt++) {
        int r0 = wm + mt * 16 + (lane >> 2);
#pragma unroll
        for (int nt = 0; nt < 8; nt++) {
            int ccol = wn + nt * 8 + (lane & 3) * 2;
            *reinterpret_cast<float2*>(&ep[r0 * EPS + ccol]) =
                make_float2(acc[mt][nt][0], acc[mt][nt][1]);
            *reinterpret_cast<float2*>(&ep[(r0 + 8) * EPS + ccol]) =
                make_float2(acc[mt][nt][2], acc[mt][nt][3]);
        }
    }
    __syncthreads();

#pragma unroll
    for (int i = 0; i < 16; i++) {
        int idx = tid + 256 * i;
        int row = idx >> 5, c4 = (idx & 31) * 4;
        float4 v = *reinterpret_cast<const float4*>(&ep[row * EPS + c4]);
        float4 bv = *reinterpret_cast<const float4*>(&bias[c4]);
        float4 rv = *reinterpret_cast<const float4*>(&resid[(size_t)row * CDIM + c4]);
        v.x += bv.x + rv.x; v.y += bv.y + rv.y;
        v.z += bv.z + rv.z; v.w += bv.w + rv.w;
        *reinterpret_cast<float4*>(&outp[(size_t)row * CDIM + c4]) = v;
    }
}

// ---------------- rank-1 softmax attention (R10-proven pure ex2f) ----------------
__global__ void __launch_bounds__(512)
attn16_kernel() {
    __shared__ float sth[16 * 128], sg[16 * 128], sph[16 * 128];
    const int tid = threadIdx.x;
    const size_t base = (size_t)blockIdx.x * 16 * 128;
    reinterpret_cast<float4*>(sth)[tid] = reinterpret_cast<const float4*>(s_theta + base)[tid];
    reinterpret_cast<float4*>(sg)[tid]  = reinterpret_cast<const float4*>(s_g + base)[tid];
    reinterpret_cast<float4*>(sph)[tid] = reinterpret_cast<const float4*>(s_phi + base)[tid];
    __syncwarp();

    const int w = tid >> 5, l = tid & 31;
    const float* th = sth + w * 128;
    const float* gg = sg + w * 128;
    const float* ph = sph + w * 128;

    float a0 = th[l], a1 = th[l + 32], a2 = th[l + 64], a3 = th[l + 96];
    float mx = fmaxf(fmaxf(a0, a1), fmaxf(a2, a3));
    float mn = fminf(fminf(a0, a1), fminf(a2, a3));
#pragma unroll
    for (int off = 16; off >= 1; off >>= 1) {
        mx = fmaxf(mx, __shfl_xor_sync(0xffffffffu, mx, off));
        mn = fminf(mn, __shfl_xor_sync(0xffffffffu, mn, off));
    }
    float sc[4], m2n[4], num[4], den[4];
#pragma unroll
    for (int q = 0; q < 4; q++) {
        sc[q] = ph[l + 32 * q] * LOG2E;
        m2n[q] = -sc[q] * (sc[q] >= 0.f ? mx : mn);
        num[q] = 0.f; den[q] = 0.f;
    }
#pragma unroll 8
    for (int j = 0; j < 128; j += 4) {
        float4 tv = *reinterpret_cast<const float4*>(&th[j]);
        float4 gv = *reinterpret_cast<const float4*>(&gg[j]);
        float t_[4] = {tv.x, tv.y, tv.z, tv.w};
        float g_[4] = {gv.x, gv.y, gv.z, gv.w};
#pragma unroll
        for (int e = 0; e < 4; e++) {
#pragma unroll
            for (int q = 0; q < 4; q++) {
                float ex = ex2f(fmaf(sc[q], t_[e], m2n[q]));
                num[q] = fmaf(ex, g_[e], num[q]);
                den[q] += ex;
            }
        }
    }
#pragma unroll
    for (int q = 0; q < 4; q++)
        s_y[base + (size_t)w * 128 + l + 32 * q] = num[q] / den[q];
}

// ------------------------------- launch -------------------------------
extern "C" void kernel_launch(void* const* d_in, const int* in_sizes, int n_in,
                              void* d_out, int out_size) {
    const float* x0   = (const float*)d_in[0];
    const float* x1   = (const float*)d_in[1];
    const float* g_w  = (const float*)d_in[2];
    const float* g_b  = (const float*)d_in[3];
    const float* th_w = (const float*)d_in[4];
    const float* th_b = (const float*)d_in[5];
    const float* ph_w = (const float*)d_in[6];
    const float* ph_b = (const float*)d_in[7];
    const float* W_w  = (const float*)d_in[8];
    const float* W_b  = (const float*)d_in[9];
    float* out = (float*)d_out;

    cudaFuncSetAttribute(out_gemm, cudaFuncAttributeMaxDynamicSharedMemorySize, OUT_SMEM);
    cudaFuncSetAttribute(proj_gemm, cudaFuncAttributeMaxDynamicSharedMemorySize, PSMEM);

    split4_kernel<<<dim3(32, 4), 256>>>(g_w, th_w, ph_w, W_w);

    proj_gemm<<<dim3(3, BDIM / 128), 256, PSMEM>>>(x0, x1, g_b, th_b, ph_b);

    attn16_kernel<<<BDIM / 16, 512>>>();

    out_gemm<<<dim3(8, BDIM / 128), 256, OUT_SMEM>>>(W_b, x0, out);
}